// round 3
// baseline (speedup 1.0000x reference)
#include <cuda_runtime.h>
#include <cuda_bf16.h>

// CrossNet collapsed:
//   out = x0 * a3 + Bsum,  a recurrence: a_{l+1} = a_l + (a_l * d_l + c_l)
//   d_l = dot(x0, W[l]) (per-row), c_l = dot(Bsum_l, W[l]) (row-independent)
// Kernel 1 precomputes c1, c2, Bsum once. Kernel 2 is block-per-row with
// 1 float4 of state per thread -> low regs, high occupancy, DRAM-saturating.

#define DIMV 256   // float4s per row (DIM = 1024)

__device__ float g_c1;
__device__ float g_c2;
__device__ float4 g_bsum[DIMV];

__global__ __launch_bounds__(256) void crossnet_precompute(
    const float4* __restrict__ W,
    const float4* __restrict__ B)
{
    const int t = threadIdx.x;          // 0..255, one float4 each
    const int lane = t & 31;
    const int warp = t >> 5;

    float4 b0 = B[t];
    float4 b1 = B[DIMV + t];
    float4 b2 = B[2 * DIMV + t];
    float4 w1 = W[DIMV + t];
    float4 w2 = W[2 * DIMV + t];

    float4 bs01 = make_float4(b0.x + b1.x, b0.y + b1.y, b0.z + b1.z, b0.w + b1.w);
    g_bsum[t] = make_float4(bs01.x + b2.x, bs01.y + b2.y, bs01.z + b2.z, bs01.w + b2.w);

    float c1 = b0.x * w1.x + b0.y * w1.y + b0.z * w1.z + b0.w * w1.w;
    float c2 = bs01.x * w2.x + bs01.y * w2.y + bs01.z * w2.z + bs01.w * w2.w;

#pragma unroll
    for (int o = 16; o > 0; o >>= 1) {
        c1 += __shfl_xor_sync(0xffffffffu, c1, o);
        c2 += __shfl_xor_sync(0xffffffffu, c2, o);
    }

    __shared__ float s1[8], s2[8];
    if (lane == 0) { s1[warp] = c1; s2[warp] = c2; }
    __syncthreads();
    if (t == 0) {
        float a1 = 0.f, a2 = 0.f;
#pragma unroll
        for (int w = 0; w < 8; ++w) { a1 += s1[w]; a2 += s2[w]; }
        g_c1 = a1;
        g_c2 = a2;
    }
}

__global__ __launch_bounds__(256, 6) void crossnet_main(
    const float4* __restrict__ x0,
    const float4* __restrict__ W,
    float4* __restrict__ out)
{
    const int row = blockIdx.x;
    const int t = threadIdx.x;
    const int lane = t & 31;
    const int warp = t >> 5;

    const size_t base = (size_t)row * DIMV + t;

    float4 x = x0[base];                 // the only DRAM read
    float4 w0 = W[t];                    // L1-resident across blocks
    float4 w1 = W[DIMV + t];
    float4 w2 = W[2 * DIMV + t];

    float d0 = x.x * w0.x + x.y * w0.y + x.z * w0.z + x.w * w0.w;
    float d1 = x.x * w1.x + x.y * w1.y + x.z * w1.z + x.w * w1.w;
    float d2 = x.x * w2.x + x.y * w2.y + x.z * w2.z + x.w * w2.w;

#pragma unroll
    for (int o = 16; o > 0; o >>= 1) {
        d0 += __shfl_xor_sync(0xffffffffu, d0, o);
        d1 += __shfl_xor_sync(0xffffffffu, d1, o);
        d2 += __shfl_xor_sync(0xffffffffu, d2, o);
    }

    __shared__ float sd[3][8];
    if (lane == 0) { sd[0][warp] = d0; sd[1][warp] = d1; sd[2][warp] = d2; }
    __syncthreads();

    float t0 = 0.f, t1 = 0.f, t2 = 0.f;
#pragma unroll
    for (int w = 0; w < 8; ++w) {
        t0 += sd[0][w]; t1 += sd[1][w]; t2 += sd[2][w];
    }

    // a recurrence (c0 = 0)
    float a = 1.0f;
    float s = a * t0;              a += s;
    s = fmaf(a, t1, g_c1);         a += s;
    s = fmaf(a, t2, g_c2);         a += s;

    float4 bs = g_bsum[t];
    float4 o;
    o.x = fmaf(x.x, a, bs.x);
    o.y = fmaf(x.y, a, bs.y);
    o.z = fmaf(x.z, a, bs.z);
    o.w = fmaf(x.w, a, bs.w);
    out[base] = o;
}

extern "C" void kernel_launch(void* const* d_in, const int* in_sizes, int n_in,
                              void* d_out, int out_size)
{
    const float4* x0 = (const float4*)d_in[0];
    const float4* W  = (const float4*)d_in[1];
    const float4* B  = (const float4*)d_in[2];
    float4* out = (float4*)d_out;

    const int batch = in_sizes[0] / 1024;

    crossnet_precompute<<<1, 256>>>(W, B);
    crossnet_main<<<batch, 256>>>(x0, W, out);
}

// round 4
// speedup vs baseline: 1.3359x; 1.3359x over previous
#include <cuda_runtime.h>
#include <cuda_bf16.h>

// CrossNet collapsed:
//   out = x0 * a3 + Bsum
//   a_{l+1} = a_l + (a_l * d_l + c_l);  d_l = dot(x0_row, W[l]) per-row,
//   c_l = dot(Bsum_l, W[l]) row-independent, Bsum = B0+B1+B2.
// Single fused kernel, R=4 rows per block: W/B loaded ONCE per block
// (amortizing L1-resident traffic -- L1tex was the binding pipe), x read once,
// out written once. Row-independent c1/c2/bsum recomputed redundantly per
// block (cheap, L2-resident) to avoid a serial precompute kernel launch.

#define DIMV 256   // float4s per row (DIM = 1024)
#define R 4        // rows per block

__device__ __forceinline__ float dot4(float4 a, float4 b) {
    return fmaf(a.x, b.x, fmaf(a.y, b.y, fmaf(a.z, b.z, a.w * b.w)));
}

__global__ __launch_bounds__(256, 4) void crossnet_kernel(
    const float4* __restrict__ x0,
    const float4* __restrict__ W,
    const float4* __restrict__ Bm,
    float4* __restrict__ out,
    int batch)
{
    const int t = threadIdx.x;
    const int lane = t & 31;
    const int warp = t >> 5;
    const int row0 = blockIdx.x * R;

    // Block-amortized loads (L1/L2 resident across all blocks)
    float4 w0 = W[t];
    float4 w1 = W[DIMV + t];
    float4 w2 = W[2 * DIMV + t];
    float4 b0 = Bm[t];
    float4 b1 = Bm[DIMV + t];
    float4 b2 = Bm[2 * DIMV + t];

    float4 bs01 = make_float4(b0.x + b1.x, b0.y + b1.y, b0.z + b1.z, b0.w + b1.w);
    float4 bsum = make_float4(bs01.x + b2.x, bs01.y + b2.y, bs01.z + b2.z, bs01.w + b2.w);

    // 14 reduction quantities: q = 3r+l -> d_l(row r);  q=12 -> c1;  q=13 -> c2
    float v[14];
    v[12] = dot4(b0, w1);
    v[13] = dot4(bs01, w2);

    float4 x[R];
#pragma unroll
    for (int r = 0; r < R; ++r) {
        x[r] = x0[(size_t)(row0 + r) * DIMV + t];   // the only DRAM reads
        v[3 * r + 0] = dot4(x[r], w0);
        v[3 * r + 1] = dot4(x[r], w1);
        v[3 * r + 2] = dot4(x[r], w2);
    }

    // Warp-level tree reduction of all 14 values (independent chains)
#pragma unroll
    for (int o = 16; o > 0; o >>= 1) {
#pragma unroll
        for (int q = 0; q < 14; ++q)
            v[q] += __shfl_xor_sync(0xffffffffu, v[q], o);
    }

    __shared__ float sd[14][8];
    __shared__ float sa[R];
    if (lane == 0) {
#pragma unroll
        for (int q = 0; q < 14; ++q) sd[q][warp] = v[q];
    }
    __syncthreads();

    // Warp 0 finishes: lane q sums 8 warp partials, then shuffles assemble
    // per-row scalars; lanes 0..R-1 run the recurrence and publish a[r].
    if (warp == 0) {
        float S = 0.0f;
        if (lane < 14) {
#pragma unroll
            for (int w = 0; w < 8; ++w) S += sd[lane][w];
        }
        const int r = lane;  // only lanes < R use these
        float d0 = __shfl_sync(0xffffffffu, S, (r < R ? 3 * r + 0 : 0));
        float d1 = __shfl_sync(0xffffffffu, S, (r < R ? 3 * r + 1 : 0));
        float d2 = __shfl_sync(0xffffffffu, S, (r < R ? 3 * r + 2 : 0));
        float c1 = __shfl_sync(0xffffffffu, S, 12);
        float c2 = __shfl_sync(0xffffffffu, S, 13);
        if (lane < R) {
            float a = 1.0f;
            float s = a * d0;          a += s;   // c0 == 0 exactly
            s = fmaf(a, d1, c1);       a += s;
            s = fmaf(a, d2, c2);       a += s;
            sa[lane] = a;
        }
    }
    __syncthreads();

#pragma unroll
    for (int r = 0; r < R; ++r) {
        float a = sa[r];
        float4 o;
        o.x = fmaf(x[r].x, a, bsum.x);
        o.y = fmaf(x[r].y, a, bsum.y);
        o.z = fmaf(x[r].z, a, bsum.z);
        o.w = fmaf(x[r].w, a, bsum.w);
        out[(size_t)(row0 + r) * DIMV + t] = o;
    }
}

extern "C" void kernel_launch(void* const* d_in, const int* in_sizes, int n_in,
                              void* d_out, int out_size)
{
    const float4* x0 = (const float4*)d_in[0];
    const float4* W  = (const float4*)d_in[1];
    const float4* B  = (const float4*)d_in[2];
    float4* out = (float4*)d_out;

    const int batch = in_sizes[0] / 1024;   // 16384, divisible by R
    crossnet_kernel<<<batch / R, 256>>>(x0, W, B, out, batch);
}